// round 15
// baseline (speedup 1.0000x reference)
#include <cuda_runtime.h>
#include <cuda_bf16.h>
#include <cuda_fp16.h>
#include <cstdint>

#define B_  4
#define T_  64
#define S_  256
#define E_  512
#define D_  512
#define F_  128

#define LOG2E 1.4426950408889634f
#define SCH 8
#define TT  8

// GEMM: 128x64 tile, 256 threads, 8 warps (4m x 2n, warp tile 32x32),
// fp16 m16n8k16, K chunks of 32 halfs, 3-stage cp.async ring.
#define BM 128
#define BN 64
#define RSTR 40                                    // halfs per row (80 B)
#define A_BYTES (BM * RSTR * 2)                    // 10240
#define W_BYTES (BN * RSTR * 2)                    // 5120
#define STG_BYTES (A_BYTES + W_BYTES)              // 15360
#define NSTG 3
#define GEMM_SMEM_BYTES (STG_BYTES * NSTG)         // 46080

// -------- scratch (device globals) --------
__device__ float g_out_hs [S_ * B_ * D_];
__device__ float g_out_fds[B_ * S_ * D_];
__device__ float g_o2p    [B_ * T_ * D_];
__device__ float g_o3p    [B_ * T_ * D_];
__device__ float g_ps1    [B_ * T_ * SCH * D_];
__device__ float g_ps2    [B_ * T_ * SCH * D_];
__device__ int   g_cnt    [B_ * (T_ / TT) * (D_ / 128)];   // 128 counters
// fp16 copies of GEMM inputs
__device__ __half g_enc_h[S_ * B_ * E_];
__device__ __half g_out_h[B_ * T_ * D_];
__device__ __half g_z_h  [B_ * S_ * F_];
__device__ __half g_W1h[D_ * E_];
__device__ __half g_W2h[D_ * D_];
__device__ __half g_W3h[D_ * F_];
__device__ __half g_W4h[D_ * D_];

__device__ __forceinline__ uint32_t smem_u32(const void* p) {
    uint32_t a;
    asm("{ .reg .u64 t; cvta.to.shared.u64 t, %1; cvt.u32.u64 %0, t; }"
        : "=r"(a) : "l"(p));
    return a;
}
__device__ __forceinline__ void cp16(uint32_t dst, const void* src) {
    asm volatile("cp.async.cg.shared.global [%0], [%1], 16;"
                 :: "r"(dst), "l"(src));
}

// ============================================================================
// Convert fp32 -> fp16 (rn), and zero the reduction counters.
// ============================================================================
struct CVD { const float* s; __half* d; int base; };
struct CVDs { CVD p[7]; int* cnt; };

__global__ void __launch_bounds__(256)
convert_fp16(CVDs P)
{
    int bx = blockIdx.x;
    if (bx == 0 && threadIdx.x < 128) P.cnt[threadIdx.x] = 0;

    int gi = 0;
#pragma unroll
    for (int i = 1; i < 7; i++) if (bx >= P.p[i].base) gi = i;
    const CVD c = P.p[gi];
    int idx = (bx - c.base) * 1024 + threadIdx.x * 4;
    float4 v = *(const float4*)&c.s[idx];
    __half2 h0 = __floats2half2_rn(v.x, v.y);
    __half2 h1 = __floats2half2_rn(v.z, v.w);
    *(__half2*)&c.d[idx]     = h0;
    *(__half2*)&c.d[idx + 2] = h1;
}

// ============================================================================
// Fused 4-in-1 GEMM, fp16 m16n8k16, fp32 accumulate. (unchanged from R14)
// C = tanh(A @ W^T + bias) [* log2e]
// ============================================================================
struct Desc {
    const __half *A, *W;
    const float* bias;
    float *C;
    int K, mode, base;
};
struct Descs { Desc d[4]; };

__global__ void __launch_bounds__(256)
fused_gemm_f16(Descs P)
{
    extern __shared__ char smem[];

    int bx = blockIdx.x;
    int gi;
    if      (bx >= P.d[3].base) gi = 3;
    else if (bx >= P.d[2].base) gi = 2;
    else if (bx >= P.d[1].base) gi = 1;
    else                        gi = 0;
    const Desc dsc = P.d[gi];

    int local = bx - dsc.base;
    int bm = local >> 3;
    int bn = local & 7;
    int m0 = bm * BM, n0 = bn * BN;
    const int K = dsc.K;
    const int nk = K >> 5;

    int tid  = threadIdx.x;
    int lane = tid & 31;
    int w    = tid >> 5;
    int wm   = w & 3;
    int wn   = w >> 2;
    int fr   = lane >> 2;
    int fc   = lane & 3;

    int arow = tid >> 1;
    int acs  = (tid & 1) * 2;
    int brow = tid >> 2;
    int bcs  = tid & 3;

    int g     = lane >> 3;
    int trow  = (g & 1) * 8 + (lane & 7);
    int tcolh = (g >> 1) * 8;

    uint32_t sbase = smem_u32(smem);
    uint32_t a_lm = sbase + (uint32_t)((wm * 32 + trow) * (RSTR * 2));
    uint32_t w_lm = sbase + (uint32_t)(A_BYTES + (wn * 32 + trow) * (RSTR * 2));

    const __half* Ag = dsc.A + (size_t)(m0 + arow) * K + acs * 8;
    const __half* Wg = dsc.W + (size_t)(n0 + brow) * K + bcs * 8;

    auto issue = [&](int ks, int stg) {
        uint32_t sb = sbase + (uint32_t)(stg * STG_BYTES);
        int koff = ks << 5;
        uint32_t da = sb + (uint32_t)(arow * (RSTR * 2) + acs * 16);
        uint32_t dw = sb + (uint32_t)(A_BYTES + brow * (RSTR * 2) + bcs * 16);
        cp16(da,      Ag + koff);
        cp16(da + 16, Ag + koff + 8);
        cp16(dw,      Wg + koff);
        asm volatile("cp.async.commit_group;" ::: "memory");
    };

    float acc[2][4][4];
#pragma unroll
    for (int a = 0; a < 2; a++)
#pragma unroll
        for (int b = 0; b < 4; b++)
#pragma unroll
            for (int c = 0; c < 4; c++) acc[a][b][c] = 0.f;

    issue(0, 0);
    issue(1, 1);

    for (int ks = 0; ks < nk; ks++) {
        if (ks + 1 < nk) asm volatile("cp.async.wait_group 1;" ::: "memory");
        else             asm volatile("cp.async.wait_group 0;" ::: "memory");
        __syncthreads();

        if (ks + 2 < nk) issue(ks + 2, (ks + 2) % 3);

        uint32_t abase = a_lm + (uint32_t)((ks % 3) * STG_BYTES);
        uint32_t wbase = w_lm + (uint32_t)((ks % 3) * STG_BYTES);
#pragma unroll
        for (int kq = 0; kq < 2; kq++) {
            uint32_t a[2][4];
#pragma unroll
            for (int mf = 0; mf < 2; mf++) {
                uint32_t ad = abase +
                    (uint32_t)((mf * 16) * (RSTR * 2) + (kq * 16 + tcolh) * 2);
                asm volatile(
                    "ldmatrix.sync.aligned.m8n8.x4.shared.b16 {%0,%1,%2,%3}, [%4];"
                    : "=r"(a[mf][0]), "=r"(a[mf][1]), "=r"(a[mf][2]), "=r"(a[mf][3])
                    : "r"(ad));
            }
            uint32_t b[4][2];
#pragma unroll
            for (int np = 0; np < 2; np++) {
                uint32_t r0, r1, r2, r3;
                uint32_t wd = wbase +
                    (uint32_t)((np * 16) * (RSTR * 2) + (kq * 16 + tcolh) * 2);
                asm volatile(
                    "ldmatrix.sync.aligned.m8n8.x4.shared.b16 {%0,%1,%2,%3}, [%4];"
                    : "=r"(r0), "=r"(r1), "=r"(r2), "=r"(r3) : "r"(wd));
                b[2 * np][0] = r0; b[2 * np + 1][0] = r1;
                b[2 * np][1] = r2; b[2 * np + 1][1] = r3;
            }
#pragma unroll
            for (int nf = 0; nf < 4; nf++)
#pragma unroll
                for (int mf = 0; mf < 2; mf++) {
                    asm volatile(
                        "mma.sync.aligned.m16n8k16.row.col.f32.f16.f16.f32 "
                        "{%0,%1,%2,%3}, {%4,%5,%6,%7}, {%8,%9}, {%0,%1,%2,%3};"
                        : "+f"(acc[mf][nf][0]), "+f"(acc[mf][nf][1]),
                          "+f"(acc[mf][nf][2]), "+f"(acc[mf][nf][3])
                        : "r"(a[mf][0]), "r"(a[mf][1]), "r"(a[mf][2]),
                          "r"(a[mf][3]), "r"(b[nf][0]), "r"(b[nf][1]));
                }
        }
    }

#pragma unroll
    for (int mf = 0; mf < 2; mf++) {
        int r0 = m0 + wm * 32 + mf * 16 + fr;
#pragma unroll
        for (int nf = 0; nf < 4; nf++) {
            int col = n0 + wn * 32 + nf * 8 + 2 * fc;
            float bb0 = dsc.bias[col];
            float bb1 = dsc.bias[col + 1];
            float v0 = tanhf(acc[mf][nf][0] + bb0);
            float v1 = tanhf(acc[mf][nf][1] + bb1);
            float v2 = tanhf(acc[mf][nf][2] + bb0);
            float v3 = tanhf(acc[mf][nf][3] + bb1);
            if (dsc.mode) { v0 *= LOG2E; v1 *= LOG2E; v2 *= LOG2E; v3 *= LOG2E; }
            *(float2*)&dsc.C[(size_t)r0       * D_ + col] = make_float2(v0, v1);
            *(float2*)&dsc.C[(size_t)(r0 + 8) * D_ + col] = make_float2(v2, v3);
        }
    }
}

// ============================================================================
// Attention partial + FUSED finalize (threadfence-reduction pattern).
// Grid: x = d-chunk (4), y = t-tile (8), z = b*SCH+sc (32) -> 1024 blocks.
// The last block of each (b, t-tile, d-chunk) group reduces all SCH slices
// in FIXED sc order (deterministic) and writes concat (+attn).
// ============================================================================
__global__ void __launch_bounds__(128)
dual_attn_fused(const float* __restrict__ out_hs,
                const float* __restrict__ out_fds,
                const float* __restrict__ enc,
                const float* __restrict__ o2p,
                const float* __restrict__ o3p,
                const float* __restrict__ outp,
                float* __restrict__ ps1,
                float* __restrict__ ps2,
                int* __restrict__ cnt,
                float* __restrict__ concat,
                float* __restrict__ attn_out)
{
    int d  = blockIdx.x * 128 + threadIdx.x;
    int t0 = blockIdx.y * TT;
    int bz = blockIdx.z;
    int b  = bz >> 3;
    int sc = bz & 7;

    float o2[TT], o3[TT], s1[TT], s2[TT];
#pragma unroll
    for (int i = 0; i < TT; i++) {
        int r = b * T_ + t0 + i;
        o2[i] = o2p[r * D_ + d];
        o3[i] = o3p[r * D_ + d];
        s1[i] = 0.f;
        s2[i] = 0.f;
    }

    const int SC = S_ / SCH;   // 32
    size_t base = ((size_t)b * S_ + sc * SC) * D_ + d;

    for (int s = 0; s < SC; s += 4) {
        float hh[4], ff[4], ee[4];
#pragma unroll
        for (int u = 0; u < 4; u++) hh[u] = out_hs [base + u * D_];
#pragma unroll
        for (int u = 0; u < 4; u++) ff[u] = out_fds[base + u * D_];
#pragma unroll
        for (int u = 0; u < 4; u++) ee[u] = enc    [base + u * D_];
        base += 4 * D_;
#pragma unroll
        for (int u = 0; u < 4; u++) {
#pragma unroll
            for (int i = 0; i < TT; i++) {
                float g = fmaf(hh[u], o2[i], ff[u] * o3[i]);
                float ex;
                asm("ex2.approx.f32 %0, %1;" : "=f"(ex) : "f"(g));
                s1[i] += ex;
                s2[i] = fmaf(ex, ee[u], s2[i]);
            }
        }
    }

    // publish partials
#pragma unroll
    for (int i = 0; i < TT; i++) {
        size_t idx = (((size_t)(b * T_ + t0 + i)) * SCH + sc) * D_ + d;
        ps1[idx] = s1[i];
        ps2[idx] = s2[i];
    }
    __threadfence();

    __shared__ int s_last;
    if (threadIdx.x == 0) {
        int grp = (b * (T_ / TT) + blockIdx.y) * (D_ / 128) + blockIdx.x;
        s_last = atomicAdd(&cnt[grp], 1);
    }
    __syncthreads();

    if (s_last == SCH - 1) {
        // this block reduces all SCH slices for its 8 rows (fixed order)
#pragma unroll
        for (int i = 0; i < TT; i++) {
            int r = b * T_ + t0 + i;
            size_t pb = ((size_t)r * SCH) * D_ + d;
            float a0 = 0.f, a1 = 0.f;
#pragma unroll
            for (int s = 0; s < SCH; s++) {
                a0 += ps1[pb + (size_t)s * D_];
                a1 += ps2[pb + (size_t)s * D_];
            }
            float at = a1 / a0;
            concat[(size_t)r * (2 * D_) + d]      = outp[(size_t)r * D_ + d];
            concat[(size_t)r * (2 * D_) + D_ + d] = at;
            if (attn_out) attn_out[(size_t)r * D_ + d] = at;
        }
    }
}

// ============================================================================
// kernel_launch
// ============================================================================
extern "C" void kernel_launch(void* const* d_in, const int* in_sizes, int n_in,
                              void* d_out, int out_size)
{
    const float* output = (const float*)d_in[0];
    const float* enc    = (const float*)d_in[1];
    const float* z      = (const float*)d_in[2];
    const float* W1 = (const float*)d_in[3];
    const float* b1 = (const float*)d_in[4];
    const float* W2 = (const float*)d_in[5];
    const float* b2 = (const float*)d_in[6];
    const float* W3 = (const float*)d_in[7];
    const float* b3 = (const float*)d_in[8];
    const float* W4 = (const float*)d_in[9];
    const float* b4 = (const float*)d_in[10];

    float *p_hs, *p_fds, *p_o2, *p_o3, *p_s1, *p_s2;
    int* p_cnt;
    __half *h_enc, *h_out, *h_z, *h_W1, *h_W2, *h_W3, *h_W4;
    cudaGetSymbolAddress((void**)&p_hs,  g_out_hs);
    cudaGetSymbolAddress((void**)&p_fds, g_out_fds);
    cudaGetSymbolAddress((void**)&p_o2,  g_o2p);
    cudaGetSymbolAddress((void**)&p_o3,  g_o3p);
    cudaGetSymbolAddress((void**)&p_s1,  g_ps1);
    cudaGetSymbolAddress((void**)&p_s2,  g_ps2);
    cudaGetSymbolAddress((void**)&p_cnt, g_cnt);
    cudaGetSymbolAddress((void**)&h_enc, g_enc_h);
    cudaGetSymbolAddress((void**)&h_out, g_out_h);
    cudaGetSymbolAddress((void**)&h_z,   g_z_h);
    cudaGetSymbolAddress((void**)&h_W1,  g_W1h);
    cudaGetSymbolAddress((void**)&h_W2,  g_W2h);
    cudaGetSymbolAddress((void**)&h_W3,  g_W3h);
    cudaGetSymbolAddress((void**)&h_W4,  g_W4h);

    float* concat = (float*)d_out;
    const int concat_elems = B_ * T_ * 2 * D_;
    const int attn_elems   = B_ * T_ * D_;
    float* attn_out = (out_size >= concat_elems + attn_elems)
                        ? concat + concat_elems : nullptr;

    cudaFuncSetAttribute(fused_gemm_f16,
                         cudaFuncAttributeMaxDynamicSharedMemorySize,
                         GEMM_SMEM_BYTES);

    // Convert fp32 -> fp16 (+ zero counters). blocks = elems/1024.
    CVDs CV;
    CV.p[0] = { enc,    h_enc,    0 };
    CV.p[1] = { output, h_out,  512 };
    CV.p[2] = { z,      h_z,    640 };
    CV.p[3] = { W1,     h_W1,   768 };
    CV.p[4] = { W2,     h_W2,  1024 };
    CV.p[5] = { W3,     h_W3,  1280 };
    CV.p[6] = { W4,     h_W4,  1344 };
    CV.cnt  = p_cnt;
    convert_fp16<<<1600, 256>>>(CV);

    // GEMM blocks, 128x64 tiles (heavy K=512 first, light lin3 last)
    Descs P;
    P.d[0] = { h_enc, h_W1, b1, p_hs,  E_, 0,  0 };
    P.d[1] = { h_out, h_W2, b2, p_o2,  D_, 1, 64 };
    P.d[2] = { h_out, h_W4, b4, p_o3,  D_, 1, 80 };
    P.d[3] = { h_z,   h_W3, b3, p_fds, F_, 0, 96 };

    fused_gemm_f16<<<160, 256, GEMM_SMEM_BYTES>>>(P);

    dual_attn_fused<<<dim3(D_ / 128, T_ / TT, B_ * SCH), 128>>>(
        p_hs, p_fds, enc, p_o2, p_o3, output, p_s1, p_s2, p_cnt,
        concat, attn_out);
}

// round 16
// speedup vs baseline: 1.1718x; 1.1718x over previous
#include <cuda_runtime.h>
#include <cuda_bf16.h>
#include <cuda_fp16.h>
#include <cstdint>

#define B_  4
#define T_  64
#define S_  256
#define E_  512
#define D_  512
#define F_  128

#define LOG2E 1.4426950408889634f
#define SCH 8
#define TT  8

// GEMM: 128x64 tile, 256 threads, 8 warps (4m x 2n, warp tile 32x32),
// fp16 m16n8k16, K chunks of 32 halfs, 3-stage cp.async ring.
#define BM 128
#define BN 64
#define RSTR 40                                    // halfs per row (80 B)
#define A_BYTES (BM * RSTR * 2)                    // 10240
#define W_BYTES (BN * RSTR * 2)                    // 5120
#define STG_BYTES (A_BYTES + W_BYTES)              // 15360
#define NSTG 3
#define GEMM_SMEM_BYTES (STG_BYTES * NSTG)         // 46080

// -------- scratch (device globals) --------
__device__ float g_out_hs [S_ * B_ * D_];
__device__ float g_out_fds[B_ * S_ * D_];
__device__ float g_o2p    [B_ * T_ * D_];
__device__ float g_o3p    [B_ * T_ * D_];
__device__ float g_ps1    [B_ * T_ * SCH * D_];
__device__ float g_ps2    [B_ * T_ * SCH * D_];
// fp16 copies of GEMM inputs
__device__ __half g_enc_h[S_ * B_ * E_];
__device__ __half g_out_h[B_ * T_ * D_];
__device__ __half g_z_h  [B_ * S_ * F_];
__device__ __half g_W1h[D_ * E_];
__device__ __half g_W2h[D_ * D_];
__device__ __half g_W3h[D_ * F_];
__device__ __half g_W4h[D_ * D_];

__device__ __forceinline__ uint32_t smem_u32(const void* p) {
    uint32_t a;
    asm("{ .reg .u64 t; cvta.to.shared.u64 t, %1; cvt.u32.u64 %0, t; }"
        : "=r"(a) : "l"(p));
    return a;
}
__device__ __forceinline__ void cp16(uint32_t dst, const void* src) {
    asm volatile("cp.async.cg.shared.global [%0], [%1], 16;"
                 :: "r"(dst), "l"(src));
}

// ============================================================================
// Convert fp32 -> fp16 (rn). 16 floats per thread via 4 INDEPENDENT float4
// loads (MLP=4) -> latency-hiding; 4096 floats per 256-thread block.
// ============================================================================
struct CVD { const float* s; __half* d; int base; };
struct CVDs { CVD p[7]; };

__global__ void __launch_bounds__(256)
convert_fp16(CVDs P)
{
    int bx = blockIdx.x;
    int gi = 0;
#pragma unroll
    for (int i = 1; i < 7; i++) if (bx >= P.p[i].base) gi = i;
    const CVD c = P.p[gi];
    int base = (bx - c.base) * 4096 + threadIdx.x * 4;

    float4 v[4];
#pragma unroll
    for (int j = 0; j < 4; j++)
        v[j] = *(const float4*)&c.s[base + j * 1024];
#pragma unroll
    for (int j = 0; j < 4; j++) {
        int idx = base + j * 1024;
        *(__half2*)&c.d[idx]     = __floats2half2_rn(v[j].x, v[j].y);
        *(__half2*)&c.d[idx + 2] = __floats2half2_rn(v[j].z, v[j].w);
    }
}

// ============================================================================
// Fused 4-in-1 GEMM, fp16 m16n8k16, fp32 accumulate. (R14, unchanged)
// C = tanh(A @ W^T + bias) [* log2e]
// ============================================================================
struct Desc {
    const __half *A, *W;
    const float* bias;
    float *C;
    int K, mode, base;
};
struct Descs { Desc d[4]; };

__global__ void __launch_bounds__(256)
fused_gemm_f16(Descs P)
{
    extern __shared__ char smem[];

    int bx = blockIdx.x;
    int gi;
    if      (bx >= P.d[3].base) gi = 3;
    else if (bx >= P.d[2].base) gi = 2;
    else if (bx >= P.d[1].base) gi = 1;
    else                        gi = 0;
    const Desc dsc = P.d[gi];

    int local = bx - dsc.base;
    int bm = local >> 3;
    int bn = local & 7;
    int m0 = bm * BM, n0 = bn * BN;
    const int K = dsc.K;
    const int nk = K >> 5;

    int tid  = threadIdx.x;
    int lane = tid & 31;
    int w    = tid >> 5;
    int wm   = w & 3;
    int wn   = w >> 2;
    int fr   = lane >> 2;
    int fc   = lane & 3;

    int arow = tid >> 1;
    int acs  = (tid & 1) * 2;
    int brow = tid >> 2;
    int bcs  = tid & 3;

    int g     = lane >> 3;
    int trow  = (g & 1) * 8 + (lane & 7);
    int tcolh = (g >> 1) * 8;

    uint32_t sbase = smem_u32(smem);
    uint32_t a_lm = sbase + (uint32_t)((wm * 32 + trow) * (RSTR * 2));
    uint32_t w_lm = sbase + (uint32_t)(A_BYTES + (wn * 32 + trow) * (RSTR * 2));

    const __half* Ag = dsc.A + (size_t)(m0 + arow) * K + acs * 8;
    const __half* Wg = dsc.W + (size_t)(n0 + brow) * K + bcs * 8;

    auto issue = [&](int ks, int stg) {
        uint32_t sb = sbase + (uint32_t)(stg * STG_BYTES);
        int koff = ks << 5;
        uint32_t da = sb + (uint32_t)(arow * (RSTR * 2) + acs * 16);
        uint32_t dw = sb + (uint32_t)(A_BYTES + brow * (RSTR * 2) + bcs * 16);
        cp16(da,      Ag + koff);
        cp16(da + 16, Ag + koff + 8);
        cp16(dw,      Wg + koff);
        asm volatile("cp.async.commit_group;" ::: "memory");
    };

    float acc[2][4][4];
#pragma unroll
    for (int a = 0; a < 2; a++)
#pragma unroll
        for (int b = 0; b < 4; b++)
#pragma unroll
            for (int c = 0; c < 4; c++) acc[a][b][c] = 0.f;

    issue(0, 0);
    issue(1, 1);

    for (int ks = 0; ks < nk; ks++) {
        if (ks + 1 < nk) asm volatile("cp.async.wait_group 1;" ::: "memory");
        else             asm volatile("cp.async.wait_group 0;" ::: "memory");
        __syncthreads();

        if (ks + 2 < nk) issue(ks + 2, (ks + 2) % 3);

        uint32_t abase = a_lm + (uint32_t)((ks % 3) * STG_BYTES);
        uint32_t wbase = w_lm + (uint32_t)((ks % 3) * STG_BYTES);
#pragma unroll
        for (int kq = 0; kq < 2; kq++) {
            uint32_t a[2][4];
#pragma unroll
            for (int mf = 0; mf < 2; mf++) {
                uint32_t ad = abase +
                    (uint32_t)((mf * 16) * (RSTR * 2) + (kq * 16 + tcolh) * 2);
                asm volatile(
                    "ldmatrix.sync.aligned.m8n8.x4.shared.b16 {%0,%1,%2,%3}, [%4];"
                    : "=r"(a[mf][0]), "=r"(a[mf][1]), "=r"(a[mf][2]), "=r"(a[mf][3])
                    : "r"(ad));
            }
            uint32_t b[4][2];
#pragma unroll
            for (int np = 0; np < 2; np++) {
                uint32_t r0, r1, r2, r3;
                uint32_t wd = wbase +
                    (uint32_t)((np * 16) * (RSTR * 2) + (kq * 16 + tcolh) * 2);
                asm volatile(
                    "ldmatrix.sync.aligned.m8n8.x4.shared.b16 {%0,%1,%2,%3}, [%4];"
                    : "=r"(r0), "=r"(r1), "=r"(r2), "=r"(r3) : "r"(wd));
                b[2 * np][0] = r0; b[2 * np + 1][0] = r1;
                b[2 * np][1] = r2; b[2 * np + 1][1] = r3;
            }
#pragma unroll
            for (int nf = 0; nf < 4; nf++)
#pragma unroll
                for (int mf = 0; mf < 2; mf++) {
                    asm volatile(
                        "mma.sync.aligned.m16n8k16.row.col.f32.f16.f16.f32 "
                        "{%0,%1,%2,%3}, {%4,%5,%6,%7}, {%8,%9}, {%0,%1,%2,%3};"
                        : "+f"(acc[mf][nf][0]), "+f"(acc[mf][nf][1]),
                          "+f"(acc[mf][nf][2]), "+f"(acc[mf][nf][3])
                        : "r"(a[mf][0]), "r"(a[mf][1]), "r"(a[mf][2]),
                          "r"(a[mf][3]), "r"(b[nf][0]), "r"(b[nf][1]));
                }
        }
    }

#pragma unroll
    for (int mf = 0; mf < 2; mf++) {
        int r0 = m0 + wm * 32 + mf * 16 + fr;
#pragma unroll
        for (int nf = 0; nf < 4; nf++) {
            int col = n0 + wn * 32 + nf * 8 + 2 * fc;
            float bb0 = dsc.bias[col];
            float bb1 = dsc.bias[col + 1];
            float v0 = tanhf(acc[mf][nf][0] + bb0);
            float v1 = tanhf(acc[mf][nf][1] + bb1);
            float v2 = tanhf(acc[mf][nf][2] + bb0);
            float v3 = tanhf(acc[mf][nf][3] + bb1);
            if (dsc.mode) { v0 *= LOG2E; v1 *= LOG2E; v2 *= LOG2E; v3 *= LOG2E; }
            *(float2*)&dsc.C[(size_t)r0       * D_ + col] = make_float2(v0, v1);
            *(float2*)&dsc.C[(size_t)(r0 + 8) * D_ + col] = make_float2(v2, v3);
        }
    }
}

// ============================================================================
// Attention partial over S/SCH = 32 encoder positions per block. (R14)
// ============================================================================
__global__ void __launch_bounds__(128)
dual_attn_partial(const float* __restrict__ out_hs,
                  const float* __restrict__ out_fds,
                  const float* __restrict__ enc,
                  const float* __restrict__ o2p,
                  const float* __restrict__ o3p,
                  float* __restrict__ ps1,
                  float* __restrict__ ps2)
{
    int d  = blockIdx.x * 128 + threadIdx.x;
    int t0 = blockIdx.y * TT;
    int bz = blockIdx.z;
    int b  = bz >> 3;
    int sc = bz & 7;

    float o2[TT], o3[TT], s1[TT], s2[TT];
#pragma unroll
    for (int i = 0; i < TT; i++) {
        int r = b * T_ + t0 + i;
        o2[i] = o2p[r * D_ + d];
        o3[i] = o3p[r * D_ + d];
        s1[i] = 0.f;
        s2[i] = 0.f;
    }

    const int SC = S_ / SCH;   // 32
    size_t base = ((size_t)b * S_ + sc * SC) * D_ + d;

    for (int s = 0; s < SC; s += 4) {
        float hh[4], ff[4], ee[4];
#pragma unroll
        for (int u = 0; u < 4; u++) hh[u] = out_hs [base + u * D_];
#pragma unroll
        for (int u = 0; u < 4; u++) ff[u] = out_fds[base + u * D_];
#pragma unroll
        for (int u = 0; u < 4; u++) ee[u] = enc    [base + u * D_];
        base += 4 * D_;
#pragma unroll
        for (int u = 0; u < 4; u++) {
#pragma unroll
            for (int i = 0; i < TT; i++) {
                float g = fmaf(hh[u], o2[i], ff[u] * o3[i]);
                float ex;
                asm("ex2.approx.f32 %0, %1;" : "=f"(ex) : "f"(g));
                s1[i] += ex;
                s2[i] = fmaf(ex, ee[u], s2[i]);
            }
        }
    }

#pragma unroll
    for (int i = 0; i < TT; i++) {
        size_t idx = (((size_t)(b * T_ + t0 + i)) * SCH + sc) * D_ + d;
        ps1[idx] = s1[i];
        ps2[idx] = s2[i];
    }
}

// ============================================================================
// Finalize: reduce SCH partials, divide, write concat (+attn). (R14)
// ============================================================================
__global__ void __launch_bounds__(128)
attn_finalize(const float* __restrict__ ps1,
              const float* __restrict__ ps2,
              const float* __restrict__ outp,
              float* __restrict__ concat,
              float* __restrict__ attn_out)
{
    int d = blockIdx.x * 128 + threadIdx.x;
    int r = blockIdx.z * T_ + blockIdx.y;

    size_t base = ((size_t)r * SCH) * D_ + d;
    float a0 = 0.f, a1 = 0.f;
#pragma unroll
    for (int sc = 0; sc < SCH; sc++) {
        a0 += ps1[base + (size_t)sc * D_];
        a1 += ps2[base + (size_t)sc * D_];
    }
    float at = a1 / a0;
    concat[(size_t)r * (2 * D_) + d]      = outp[(size_t)r * D_ + d];
    concat[(size_t)r * (2 * D_) + D_ + d] = at;
    if (attn_out) attn_out[(size_t)r * D_ + d] = at;
}

// ============================================================================
// kernel_launch
// ============================================================================
extern "C" void kernel_launch(void* const* d_in, const int* in_sizes, int n_in,
                              void* d_out, int out_size)
{
    const float* output = (const float*)d_in[0];
    const float* enc    = (const float*)d_in[1];
    const float* z      = (const float*)d_in[2];
    const float* W1 = (const float*)d_in[3];
    const float* b1 = (const float*)d_in[4];
    const float* W2 = (const float*)d_in[5];
    const float* b2 = (const float*)d_in[6];
    const float* W3 = (const float*)d_in[7];
    const float* b3 = (const float*)d_in[8];
    const float* W4 = (const float*)d_in[9];
    const float* b4 = (const float*)d_in[10];

    float *p_hs, *p_fds, *p_o2, *p_o3, *p_s1, *p_s2;
    __half *h_enc, *h_out, *h_z, *h_W1, *h_W2, *h_W3, *h_W4;
    cudaGetSymbolAddress((void**)&p_hs,  g_out_hs);
    cudaGetSymbolAddress((void**)&p_fds, g_out_fds);
    cudaGetSymbolAddress((void**)&p_o2,  g_o2p);
    cudaGetSymbolAddress((void**)&p_o3,  g_o3p);
    cudaGetSymbolAddress((void**)&p_s1,  g_ps1);
    cudaGetSymbolAddress((void**)&p_s2,  g_ps2);
    cudaGetSymbolAddress((void**)&h_enc, g_enc_h);
    cudaGetSymbolAddress((void**)&h_out, g_out_h);
    cudaGetSymbolAddress((void**)&h_z,   g_z_h);
    cudaGetSymbolAddress((void**)&h_W1,  g_W1h);
    cudaGetSymbolAddress((void**)&h_W2,  g_W2h);
    cudaGetSymbolAddress((void**)&h_W3,  g_W3h);
    cudaGetSymbolAddress((void**)&h_W4,  g_W4h);

    float* concat = (float*)d_out;
    const int concat_elems = B_ * T_ * 2 * D_;
    const int attn_elems   = B_ * T_ * D_;
    float* attn_out = (out_size >= concat_elems + attn_elems)
                        ? concat + concat_elems : nullptr;

    cudaFuncSetAttribute(fused_gemm_f16,
                         cudaFuncAttributeMaxDynamicSharedMemorySize,
                         GEMM_SMEM_BYTES);

    // Convert fp32 -> fp16. blocks = elems/4096:
    // enc 128 (0), out 32 (128), z 32 (160), W1 64 (192),
    // W2 64 (256), W3 16 (320), W4 64 (336) -> 400 blocks
    CVDs CV;
    CV.p[0] = { enc,    h_enc,    0 };
    CV.p[1] = { output, h_out,  128 };
    CV.p[2] = { z,      h_z,    160 };
    CV.p[3] = { W1,     h_W1,   192 };
    CV.p[4] = { W2,     h_W2,   256 };
    CV.p[5] = { W3,     h_W3,   320 };
    CV.p[6] = { W4,     h_W4,   336 };
    convert_fp16<<<400, 256>>>(CV);

    // GEMM blocks, 128x64 tiles (heavy K=512 first, light lin3 last)
    Descs P;
    P.d[0] = { h_enc, h_W1, b1, p_hs,  E_, 0,  0 };
    P.d[1] = { h_out, h_W2, b2, p_o2,  D_, 1, 64 };
    P.d[2] = { h_out, h_W4, b4, p_o3,  D_, 1, 80 };
    P.d[3] = { h_z,   h_W3, b3, p_fds, F_, 0, 96 };

    fused_gemm_f16<<<160, 256, GEMM_SMEM_BYTES>>>(P);

    dual_attn_partial<<<dim3(D_ / 128, T_ / TT, B_ * SCH), 128>>>(
        p_hs, p_fds, enc, p_o2, p_o3, p_s1, p_s2);

    attn_finalize<<<dim3(4, T_, B_), 128>>>(
        p_s1, p_s2, output, concat, attn_out);
}

// round 17
// speedup vs baseline: 1.2529x; 1.0692x over previous
#include <cuda_runtime.h>
#include <cuda_bf16.h>
#include <cuda_fp16.h>
#include <cstdint>

#define B_  4
#define T_  64
#define S_  256
#define E_  512
#define D_  512
#define F_  128

#define LOG2E 1.4426950408889634f
#define SCH 8
#define TT  8

// GEMM: 128x64 tile, 256 threads, 8 warps (4m x 2n, warp tile 32x32),
// fp16 m16n8k16, K chunks of 32 halfs, 3-stage cp.async ring.
#define BM 128
#define BN 64
#define RSTR 40                                    // halfs per row (80 B)
#define A_BYTES (BM * RSTR * 2)                    // 10240
#define W_BYTES (BN * RSTR * 2)                    // 5120
#define STG_BYTES (A_BYTES + W_BYTES)              // 15360
#define NSTG 3
#define GEMM_SMEM_BYTES (STG_BYTES * NSTG)         // 46080

// attention: 64 KB dynamic smem (2 x 8sc x 8i x 128d floats)
#define ATT_SMEM_BYTES (2 * SCH * TT * 128 * 4)    // 65536

// -------- scratch (device globals) --------
__device__ float g_out_hs [S_ * B_ * D_];
__device__ float g_out_fds[B_ * S_ * D_];
__device__ float g_o2p    [B_ * T_ * D_];
__device__ float g_o3p    [B_ * T_ * D_];
// fp16 copies of GEMM inputs
__device__ __half g_enc_h[S_ * B_ * E_];
__device__ __half g_out_h[B_ * T_ * D_];
__device__ __half g_z_h  [B_ * S_ * F_];
__device__ __half g_W1h[D_ * E_];
__device__ __half g_W2h[D_ * D_];
__device__ __half g_W3h[D_ * F_];
__device__ __half g_W4h[D_ * D_];

__device__ __forceinline__ uint32_t smem_u32(const void* p) {
    uint32_t a;
    asm("{ .reg .u64 t; cvta.to.shared.u64 t, %1; cvt.u32.u64 %0, t; }"
        : "=r"(a) : "l"(p));
    return a;
}
__device__ __forceinline__ void cp16(uint32_t dst, const void* src) {
    asm volatile("cp.async.cg.shared.global [%0], [%1], 16;"
                 :: "r"(dst), "l"(src));
}

// ============================================================================
// Convert fp32 -> fp16 (rn). 16 floats/thread via 4 independent float4 loads.
// ============================================================================
struct CVD { const float* s; __half* d; int base; };
struct CVDs { CVD p[7]; };

__global__ void __launch_bounds__(256)
convert_fp16(CVDs P)
{
    int bx = blockIdx.x;
    int gi = 0;
#pragma unroll
    for (int i = 1; i < 7; i++) if (bx >= P.p[i].base) gi = i;
    const CVD c = P.p[gi];
    int base = (bx - c.base) * 4096 + threadIdx.x * 4;

    float4 v[4];
#pragma unroll
    for (int j = 0; j < 4; j++)
        v[j] = *(const float4*)&c.s[base + j * 1024];
#pragma unroll
    for (int j = 0; j < 4; j++) {
        int idx = base + j * 1024;
        *(__half2*)&c.d[idx]     = __floats2half2_rn(v[j].x, v[j].y);
        *(__half2*)&c.d[idx + 2] = __floats2half2_rn(v[j].z, v[j].w);
    }
}

// ============================================================================
// Fused 4-in-1 GEMM, fp16 m16n8k16, fp32 accumulate. (R14, unchanged)
// C = tanh(A @ W^T + bias) [* log2e]
// ============================================================================
struct Desc {
    const __half *A, *W;
    const float* bias;
    float *C;
    int K, mode, base;
};
struct Descs { Desc d[4]; };

__global__ void __launch_bounds__(256)
fused_gemm_f16(Descs P)
{
    extern __shared__ char smem[];

    int bx = blockIdx.x;
    int gi;
    if      (bx >= P.d[3].base) gi = 3;
    else if (bx >= P.d[2].base) gi = 2;
    else if (bx >= P.d[1].base) gi = 1;
    else                        gi = 0;
    const Desc dsc = P.d[gi];

    int local = bx - dsc.base;
    int bm = local >> 3;
    int bn = local & 7;
    int m0 = bm * BM, n0 = bn * BN;
    const int K = dsc.K;
    const int nk = K >> 5;

    int tid  = threadIdx.x;
    int lane = tid & 31;
    int w    = tid >> 5;
    int wm   = w & 3;
    int wn   = w >> 2;
    int fr   = lane >> 2;
    int fc   = lane & 3;

    int arow = tid >> 1;
    int acs  = (tid & 1) * 2;
    int brow = tid >> 2;
    int bcs  = tid & 3;

    int g     = lane >> 3;
    int trow  = (g & 1) * 8 + (lane & 7);
    int tcolh = (g >> 1) * 8;

    uint32_t sbase = smem_u32(smem);
    uint32_t a_lm = sbase + (uint32_t)((wm * 32 + trow) * (RSTR * 2));
    uint32_t w_lm = sbase + (uint32_t)(A_BYTES + (wn * 32 + trow) * (RSTR * 2));

    const __half* Ag = dsc.A + (size_t)(m0 + arow) * K + acs * 8;
    const __half* Wg = dsc.W + (size_t)(n0 + brow) * K + bcs * 8;

    auto issue = [&](int ks, int stg) {
        uint32_t sb = sbase + (uint32_t)(stg * STG_BYTES);
        int koff = ks << 5;
        uint32_t da = sb + (uint32_t)(arow * (RSTR * 2) + acs * 16);
        uint32_t dw = sb + (uint32_t)(A_BYTES + brow * (RSTR * 2) + bcs * 16);
        cp16(da,      Ag + koff);
        cp16(da + 16, Ag + koff + 8);
        cp16(dw,      Wg + koff);
        asm volatile("cp.async.commit_group;" ::: "memory");
    };

    float acc[2][4][4];
#pragma unroll
    for (int a = 0; a < 2; a++)
#pragma unroll
        for (int b = 0; b < 4; b++)
#pragma unroll
            for (int c = 0; c < 4; c++) acc[a][b][c] = 0.f;

    issue(0, 0);
    issue(1, 1);

    for (int ks = 0; ks < nk; ks++) {
        if (ks + 1 < nk) asm volatile("cp.async.wait_group 1;" ::: "memory");
        else             asm volatile("cp.async.wait_group 0;" ::: "memory");
        __syncthreads();

        if (ks + 2 < nk) issue(ks + 2, (ks + 2) % 3);

        uint32_t abase = a_lm + (uint32_t)((ks % 3) * STG_BYTES);
        uint32_t wbase = w_lm + (uint32_t)((ks % 3) * STG_BYTES);
#pragma unroll
        for (int kq = 0; kq < 2; kq++) {
            uint32_t a[2][4];
#pragma unroll
            for (int mf = 0; mf < 2; mf++) {
                uint32_t ad = abase +
                    (uint32_t)((mf * 16) * (RSTR * 2) + (kq * 16 + tcolh) * 2);
                asm volatile(
                    "ldmatrix.sync.aligned.m8n8.x4.shared.b16 {%0,%1,%2,%3}, [%4];"
                    : "=r"(a[mf][0]), "=r"(a[mf][1]), "=r"(a[mf][2]), "=r"(a[mf][3])
                    : "r"(ad));
            }
            uint32_t b[4][2];
#pragma unroll
            for (int np = 0; np < 2; np++) {
                uint32_t r0, r1, r2, r3;
                uint32_t wd = wbase +
                    (uint32_t)((np * 16) * (RSTR * 2) + (kq * 16 + tcolh) * 2);
                asm volatile(
                    "ldmatrix.sync.aligned.m8n8.x4.shared.b16 {%0,%1,%2,%3}, [%4];"
                    : "=r"(r0), "=r"(r1), "=r"(r2), "=r"(r3) : "r"(wd));
                b[2 * np][0] = r0; b[2 * np + 1][0] = r1;
                b[2 * np][1] = r2; b[2 * np + 1][1] = r3;
            }
#pragma unroll
            for (int nf = 0; nf < 4; nf++)
#pragma unroll
                for (int mf = 0; mf < 2; mf++) {
                    asm volatile(
                        "mma.sync.aligned.m16n8k16.row.col.f32.f16.f16.f32 "
                        "{%0,%1,%2,%3}, {%4,%5,%6,%7}, {%8,%9}, {%0,%1,%2,%3};"
                        : "+f"(acc[mf][nf][0]), "+f"(acc[mf][nf][1]),
                          "+f"(acc[mf][nf][2]), "+f"(acc[mf][nf][3])
                        : "r"(a[mf][0]), "r"(a[mf][1]), "r"(a[mf][2]),
                          "r"(a[mf][3]), "r"(b[nf][0]), "r"(b[nf][1]));
                }
        }
    }

#pragma unroll
    for (int mf = 0; mf < 2; mf++) {
        int r0 = m0 + wm * 32 + mf * 16 + fr;
#pragma unroll
        for (int nf = 0; nf < 4; nf++) {
            int col = n0 + wn * 32 + nf * 8 + 2 * fc;
            float bb0 = dsc.bias[col];
            float bb1 = dsc.bias[col + 1];
            float v0 = tanhf(acc[mf][nf][0] + bb0);
            float v1 = tanhf(acc[mf][nf][1] + bb1);
            float v2 = tanhf(acc[mf][nf][2] + bb0);
            float v3 = tanhf(acc[mf][nf][3] + bb1);
            if (dsc.mode) { v0 *= LOG2E; v1 *= LOG2E; v2 *= LOG2E; v3 *= LOG2E; }
            *(float2*)&dsc.C[(size_t)r0       * D_ + col] = make_float2(v0, v1);
            *(float2*)&dsc.C[(size_t)(r0 + 8) * D_ + col] = make_float2(v2, v3);
        }
    }
}

// ============================================================================
// Fused attention: ONE kernel, smem reduction across s-chunks.
// Block = 1024 threads: tid = sc*128 + d_local. Each sc-group computes its
// 32-position slice (identical math/order to the old partial kernel), stores
// (s1,s2) to smem, syncs, then thread (i, d) sums sc=0..7 in FIXED order
// (bitwise identical to the old finalize) and writes concat (+attn).
// Grid: x = d-chunk (4), y = t-tile (8), z = b (4) -> 128 blocks.
// ============================================================================
__global__ void __launch_bounds__(1024)
dual_attn_all(const float* __restrict__ out_hs,
              const float* __restrict__ out_fds,
              const float* __restrict__ enc,
              const float* __restrict__ o2p,
              const float* __restrict__ o3p,
              const float* __restrict__ outp,
              float* __restrict__ concat,
              float* __restrict__ attn_out)
{
    extern __shared__ float smf[];
    float* sm1 = smf;                       // [SCH][TT][128]
    float* sm2 = smf + SCH * TT * 128;

    int tid = threadIdx.x;
    int sc  = tid >> 7;          // 0..7
    int dl  = tid & 127;
    int d   = blockIdx.x * 128 + dl;
    int t0  = blockIdx.y * TT;
    int b   = blockIdx.z;

    float o2[TT], o3[TT], s1[TT], s2[TT];
#pragma unroll
    for (int i = 0; i < TT; i++) {
        int r = b * T_ + t0 + i;
        o2[i] = o2p[r * D_ + d];
        o3[i] = o3p[r * D_ + d];
        s1[i] = 0.f;
        s2[i] = 0.f;
    }

    const int SC = S_ / SCH;     // 32
    size_t base = ((size_t)b * S_ + sc * SC) * D_ + d;

    for (int s = 0; s < SC; s += 4) {
        float hh[4], ff[4], ee[4];
#pragma unroll
        for (int u = 0; u < 4; u++) hh[u] = out_hs [base + u * D_];
#pragma unroll
        for (int u = 0; u < 4; u++) ff[u] = out_fds[base + u * D_];
#pragma unroll
        for (int u = 0; u < 4; u++) ee[u] = enc    [base + u * D_];
        base += 4 * D_;
#pragma unroll
        for (int u = 0; u < 4; u++) {
#pragma unroll
            for (int i = 0; i < TT; i++) {
                float g = fmaf(hh[u], o2[i], ff[u] * o3[i]);
                float ex;
                asm("ex2.approx.f32 %0, %1;" : "=f"(ex) : "f"(g));
                s1[i] += ex;
                s2[i] = fmaf(ex, ee[u], s2[i]);
            }
        }
    }

    // publish partials to smem
#pragma unroll
    for (int i = 0; i < TT; i++) {
        sm1[(sc * TT + i) * 128 + dl] = s1[i];
        sm2[(sc * TT + i) * 128 + dl] = s2[i];
    }
    __syncthreads();

    // reduce: thread (i = tid>>7, dl) sums sc 0..7 in fixed order
    int i = tid >> 7;            // 0..7
    float a0 = 0.f, a1 = 0.f;
#pragma unroll
    for (int s = 0; s < SCH; s++) {
        a0 += sm1[(s * TT + i) * 128 + dl];
        a1 += sm2[(s * TT + i) * 128 + dl];
    }
    float at = a1 / a0;
    int r = b * T_ + t0 + i;
    concat[(size_t)r * (2 * D_) + d]      = outp[(size_t)r * D_ + d];
    concat[(size_t)r * (2 * D_) + D_ + d] = at;
    if (attn_out) attn_out[(size_t)r * D_ + d] = at;
}

// ============================================================================
// kernel_launch
// ============================================================================
extern "C" void kernel_launch(void* const* d_in, const int* in_sizes, int n_in,
                              void* d_out, int out_size)
{
    const float* output = (const float*)d_in[0];
    const float* enc    = (const float*)d_in[1];
    const float* z      = (const float*)d_in[2];
    const float* W1 = (const float*)d_in[3];
    const float* b1 = (const float*)d_in[4];
    const float* W2 = (const float*)d_in[5];
    const float* b2 = (const float*)d_in[6];
    const float* W3 = (const float*)d_in[7];
    const float* b3 = (const float*)d_in[8];
    const float* W4 = (const float*)d_in[9];
    const float* b4 = (const float*)d_in[10];

    float *p_hs, *p_fds, *p_o2, *p_o3;
    __half *h_enc, *h_out, *h_z, *h_W1, *h_W2, *h_W3, *h_W4;
    cudaGetSymbolAddress((void**)&p_hs,  g_out_hs);
    cudaGetSymbolAddress((void**)&p_fds, g_out_fds);
    cudaGetSymbolAddress((void**)&p_o2,  g_o2p);
    cudaGetSymbolAddress((void**)&p_o3,  g_o3p);
    cudaGetSymbolAddress((void**)&h_enc, g_enc_h);
    cudaGetSymbolAddress((void**)&h_out, g_out_h);
    cudaGetSymbolAddress((void**)&h_z,   g_z_h);
    cudaGetSymbolAddress((void**)&h_W1,  g_W1h);
    cudaGetSymbolAddress((void**)&h_W2,  g_W2h);
    cudaGetSymbolAddress((void**)&h_W3,  g_W3h);
    cudaGetSymbolAddress((void**)&h_W4,  g_W4h);

    float* concat = (float*)d_out;
    const int concat_elems = B_ * T_ * 2 * D_;
    const int attn_elems   = B_ * T_ * D_;
    float* attn_out = (out_size >= concat_elems + attn_elems)
                        ? concat + concat_elems : nullptr;

    cudaFuncSetAttribute(fused_gemm_f16,
                         cudaFuncAttributeMaxDynamicSharedMemorySize,
                         GEMM_SMEM_BYTES);
    cudaFuncSetAttribute(dual_attn_all,
                         cudaFuncAttributeMaxDynamicSharedMemorySize,
                         ATT_SMEM_BYTES);

    // Convert fp32 -> fp16. blocks = elems/4096:
    CVDs CV;
    CV.p[0] = { enc,    h_enc,    0 };
    CV.p[1] = { output, h_out,  128 };
    CV.p[2] = { z,      h_z,    160 };
    CV.p[3] = { W1,     h_W1,   192 };
    CV.p[4] = { W2,     h_W2,   256 };
    CV.p[5] = { W3,     h_W3,   320 };
    CV.p[6] = { W4,     h_W4,   336 };
    convert_fp16<<<400, 256>>>(CV);

    // GEMM blocks, 128x64 tiles (heavy K=512 first, light lin3 last)
    Descs P;
    P.d[0] = { h_enc, h_W1, b1, p_hs,  E_, 0,  0 };
    P.d[1] = { h_out, h_W2, b2, p_o2,  D_, 1, 64 };
    P.d[2] = { h_out, h_W4, b4, p_o3,  D_, 1, 80 };
    P.d[3] = { h_z,   h_W3, b3, p_fds, F_, 0, 96 };

    fused_gemm_f16<<<160, 256, GEMM_SMEM_BYTES>>>(P);

    dual_attn_all<<<dim3(D_ / 128, T_ / TT, B_), 1024, ATT_SMEM_BYTES>>>(
        p_hs, p_fds, enc, p_o2, p_o3, output, concat, attn_out);
}